// round 4
// baseline (speedup 1.0000x reference)
#include <cuda_runtime.h>
#include <math.h>

#define BB 4
#define C 64
#define CIN0 32
#define H 128
#define W 128
#define HW (H*W)
#define DG 8
#define CPG 8
#define OMC 216

// ---------------- scratch (device globals; no runtime allocation) ----------------
__device__ float g_xc[BB*C*HW];       // conv0 output
__device__ float g_om[BB*OMC*HW];     // offset/mask conv output (sigmoid applied to mask part)
__device__ float g_xd[BB*C*HW];       // lrelu(deform conv) output
__device__ float g_x0[BB*C*HW];       // a0 conv output
__device__ float g_adcin[BB*C*HW];    // depthwise + eca  (input to a3)
__device__ float g_out2[BB*C*HW];     // unfold*filt + lrelu output
__device__ float g_s[BB*C];           // channel means
__device__ float g_eca[BB*C];         // eca values

// ---------------- conv 1x1: x[BB,32,HW] -> g_xc[BB,64,HW] ----------------
__global__ void __launch_bounds__(256, 2) conv1x1_kernel(const float* __restrict__ in,
                                                         const float* __restrict__ w,
                                                         const float* __restrict__ bias) {
    __shared__ float ws[C*CIN0];
    int tid = threadIdx.x;
    for (int i = tid; i < C*CIN0; i += blockDim.x) ws[i] = w[i];
    __syncthreads();
    int p = blockIdx.x * blockDim.x + tid;      // 0 .. BB*HW
    int b = p / HW, pix = p % HW;
    float acc[C];
    #pragma unroll
    for (int co = 0; co < C; co++) acc[co] = bias[co];
    const float* xin = in + b*CIN0*HW + pix;
    #pragma unroll 4
    for (int ci = 0; ci < CIN0; ci += 4) {
        float v0 = xin[ci*HW], v1 = xin[(ci+1)*HW], v2 = xin[(ci+2)*HW], v3 = xin[(ci+3)*HW];
        #pragma unroll
        for (int co = 0; co < C; co++) {
            float4 w4 = *(const float4*)&ws[co*CIN0+ci];
            acc[co] += w4.x*v0 + w4.y*v1 + w4.z*v2 + w4.w*v3;
        }
    }
    float* o = g_xc + b*C*HW + pix;
    #pragma unroll
    for (int co = 0; co < C; co++) o[co*HW] = acc[co];
}

// ---------------- generic direct conv 3x3, pad=1 ----------------
// EPI: 0=none, 1=sigmoid on out-channels >=144 (offm), 2=+2*extra (fus)
template<int CI, int EPI>
__global__ void __launch_bounds__(256, 2) conv3x3_kernel(const float* __restrict__ in,
                               const float* __restrict__ wt,
                               const float* __restrict__ bias, float* __restrict__ out,
                               int Cout, int nchunk, const float* __restrict__ extra) {
    constexpr int TW = 32, TH = 8, CO = 16, CS = 8;
    __shared__ float in_s[CS][TH+2][TW+4];   // 10 x 36 rows (padded)
    __shared__ float ws[CS][CO][12];         // 9 weights padded to 12 for float4 reads
    int tid = threadIdx.x;
    int tx = tid & 31, ty = tid >> 5;
    int bz = blockIdx.z;
    int b = bz / nchunk, chunk = bz % nchunk;
    int coBase = chunk * CO;
    int x0 = blockIdx.x * TW, y0 = blockIdx.y * TH;
    int x = x0 + tx, y = y0 + ty;

    float acc[CO];
    #pragma unroll
    for (int co = 0; co < CO; co++) {
        int gco = coBase + co;
        acc[co] = (gco < Cout) ? bias[gco] : 0.f;
    }

    // halo stage: e = tid, tid+256, ...; decompose once, walk incrementally
    for (int cb = 0; cb < CI; cb += CS) {
        __syncthreads();
        {
            int e = tid;
            int ci = e / 340; int r = e - ci*340; int yy = r / 34; int xx = r - yy*34;
            #pragma unroll
            for (int it = 0; it < 11 && e < CS*10*34; it++) {
                int gy = y0 + yy - 1, gx = x0 + xx - 1;
                float v = 0.f;
                if (gy >= 0 && gy < H && gx >= 0 && gx < W)
                    v = in[((size_t)(b*CI + cb + ci)*H + gy)*W + gx];
                in_s[ci][yy][xx] = v;
                e += 256;
                xx += 256 - 7*34;  // advance 256 = 7*34 + 18
                yy += 7;
                if (xx >= 34) { xx -= 34; yy += 1; }
                if (yy >= 10) { yy -= 10; ci += 1; }
            }
        }
        // stage weights: CS x CO x 9
        for (int e = tid; e < CS*CO*9; e += 256) {
            int ci = e / (CO*9); int r = e - ci*(CO*9); int co = r / 9; int t = r - co*9;
            int gco = coBase + co;
            ws[ci][co][t] = (gco < Cout) ? wt[((size_t)gco*CI + cb + ci)*9 + t] : 0.f;
        }
        __syncthreads();
        #pragma unroll
        for (int ci = 0; ci < CS; ci++) {
            float v[9];
            #pragma unroll
            for (int dy = 0; dy < 3; dy++)
                #pragma unroll
                for (int dx = 0; dx < 3; dx++)
                    v[dy*3+dx] = in_s[ci][ty+dy][tx+dx];
            #pragma unroll
            for (int co = 0; co < CO; co++) {
                const float* wp = &ws[ci][co][0];
                float4 a = *(const float4*)wp;
                float4 b4 = *(const float4*)(wp+4);
                float w8 = wp[8];
                acc[co] += a.x*v[0] + a.y*v[1] + a.z*v[2] + a.w*v[3]
                         + b4.x*v[4] + b4.y*v[5] + b4.z*v[6] + b4.w*v[7] + w8*v[8];
            }
        }
    }
    int gp = y*W + x;
    #pragma unroll
    for (int co = 0; co < CO; co++) {
        int gco = coBase + co;
        if (gco < Cout) {
            float r = acc[co];
            if (EPI == 1) { if (gco >= 144) r = 1.f/(1.f + expf(-r)); }
            if (EPI == 2) { r += 2.f * extra[(size_t)(b*C + gco)*HW + gp]; }
            out[((size_t)(b*Cout) + gco)*HW + gp] = r;
        }
    }
}

// ---------------- modulated deformable conv + lrelu ----------------
__global__ void __launch_bounds__(256, 2) deform_kernel(const float* __restrict__ wt,
                                                        const float* __restrict__ bias) {
    __shared__ float ws[9*CPG*C];   // [t][cic][co], staged per group (18KB)
    int tid = threadIdx.x;
    int tx = tid & 31, ty = tid >> 5;
    int b = blockIdx.z;
    int x = blockIdx.x*32 + tx, y = blockIdx.y*8 + ty;
    int p = y*W + x;

    float acc[C];
    #pragma unroll
    for (int co = 0; co < C; co++) acc[co] = bias[co];

    for (int g = 0; g < DG; g++) {
        __syncthreads();
        for (int e = tid; e < 9*CPG*C; e += 256) {
            int t = e / (CPG*C); int r = e - t*(CPG*C); int cic = r >> 6; int co = r & 63;
            ws[e] = wt[((size_t)co*C + g*CPG + cic)*9 + t];
        }
        __syncthreads();
        const float* omb = g_om + (size_t)b*OMC*HW;
        const float* xb = g_xc + (size_t)(b*C + g*CPG)*HW;
        for (int t = 0; t < 9; t++) {
            float dy = omb[(size_t)(g*9 + t)*HW + p];
            float dx = omb[(size_t)(72 + g*9 + t)*HW + p];
            float mk = omb[(size_t)(144 + g*9 + t)*HW + p];
            float py = dy + (float)(t/3) + (float)y - 1.0f;
            float px = dx + (float)(t%3) + (float)x - 1.0f;
            float fy = floorf(py), fx = floorf(px);
            int iy0 = (int)fy, ix0 = (int)fx;
            float wy = py - fy, wx = px - fx;
            bool vy0 = (iy0 >= 0 && iy0 < H), vy1 = (iy0+1 >= 0 && iy0+1 < H);
            bool vx0 = (ix0 >= 0 && ix0 < W), vx1 = (ix0+1 >= 0 && ix0+1 < W);
            int cy0 = min(max(iy0, 0), H-1), cy1 = min(max(iy0+1, 0), H-1);
            int cx0 = min(max(ix0, 0), W-1), cx1 = min(max(ix0+1, 0), W-1);
            float a00 = (vy0 && vx0) ? (1.f-wy)*(1.f-wx)*mk : 0.f;
            float a01 = (vy0 && vx1) ? (1.f-wy)*wx*mk       : 0.f;
            float a10 = (vy1 && vx0) ? wy*(1.f-wx)*mk       : 0.f;
            float a11 = (vy1 && vx1) ? wy*wx*mk             : 0.f;
            int i00 = cy0*W + cx0, i01 = cy0*W + cx1, i10 = cy1*W + cx0, i11 = cy1*W + cx1;
            #pragma unroll
            for (int cic = 0; cic < CPG; cic++) {
                const float* xc = xb + (size_t)cic*HW;
                float s = a00*xc[i00] + a01*xc[i01] + a10*xc[i10] + a11*xc[i11];
                const float* wp = &ws[(t*CPG + cic)*C];
                #pragma unroll
                for (int co4 = 0; co4 < C; co4 += 4) {
                    float4 w4 = *(const float4*)(wp + co4);
                    acc[co4+0] += w4.x*s; acc[co4+1] += w4.y*s;
                    acc[co4+2] += w4.z*s; acc[co4+3] += w4.w*s;
                }
            }
        }
    }
    float* ob = g_xd + (size_t)b*C*HW + p;
    #pragma unroll
    for (int co = 0; co < C; co++) {
        float r = acc[co];
        r = (r >= 0.f) ? r : 0.2f*r;
        ob[(size_t)co*HW] = r;
    }
}

// ---------------- mean over H,W per (b,c) ----------------
__global__ void __launch_bounds__(256) mean_kernel() {
    int bc = blockIdx.x;
    const float* pp = g_x0 + (size_t)bc*HW;
    float sum = 0.f;
    for (int i = threadIdx.x; i < HW; i += 256) sum += pp[i];
    __shared__ float red[256];
    red[threadIdx.x] = sum; __syncthreads();
    for (int st = 128; st > 0; st >>= 1) {
        if (threadIdx.x < st) red[threadIdx.x] += red[threadIdx.x + st];
        __syncthreads();
    }
    if (threadIdx.x == 0) g_s[bc] = red[0] * (1.0f/HW);
}

// ---------------- eca: conv1d(k=3,pad=1) over channels ----------------
__global__ void eca_kernel(const float* __restrict__ a2w, const float* __restrict__ a2b) {
    int i = threadIdx.x;
    if (i < BB*C) {
        int b = i / C, c = i % C;
        float l = (c > 0)     ? g_s[b*C + c - 1] : 0.f;
        float m = g_s[b*C + c];
        float r = (c < C - 1) ? g_s[b*C + c + 1] : 0.f;
        g_eca[i] = a2w[0]*l + a2w[1]*m + a2w[2]*r + a2b[0];
    }
}

// ---------------- depthwise 3x3 + eca broadcast ----------------
__global__ void __launch_bounds__(256) dw_kernel(const float* __restrict__ w,
                                                 const float* __restrict__ bias) {
    int idx = blockIdx.x*256 + threadIdx.x;     // over BB*C*HW
    int p = idx % HW; int bc = idx / HW; int c = bc % C;
    int y = p / W, x = p % W;
    const float* in = g_x0 + (size_t)bc*HW;
    float acc = bias[c] + g_eca[bc];
    #pragma unroll
    for (int t = 0; t < 9; t++) {
        int yy = y + t/3 - 1, xx = x + t%3 - 1;
        if (yy >= 0 && yy < H && xx >= 0 && xx < W) acc += w[c*9 + t] * in[yy*W + xx];
    }
    g_adcin[idx] = acc;
}

// ---------------- fused a3 (1x1 -> C*9) + unfold(x0)*filt + lrelu ----------------
__global__ void __launch_bounds__(256, 2) a3unfold_kernel(const float* __restrict__ w3,
                                                          const float* __restrict__ b3) {
    constexpr int CO = 4, CS = 8;
    __shared__ float in_s[CS][256];
    __shared__ float ws[CS][CO*9];
    int tid = threadIdx.x;
    int tx = tid & 31, ty = tid >> 5;
    int bz = blockIdx.z;
    int b = bz / (C/CO), coBase = (bz % (C/CO)) * CO;
    int x = blockIdx.x*32 + tx, y = blockIdx.y*8 + ty;
    int gp = y*W + x;

    float facc[CO*9];
    #pragma unroll
    for (int k = 0; k < CO*9; k++) facc[k] = b3[coBase*9 + k];

    for (int cb = 0; cb < C; cb += CS) {
        __syncthreads();
        #pragma unroll
        for (int ci = 0; ci < CS; ci++)
            in_s[ci][tid] = g_adcin[(size_t)(b*C + cb + ci)*HW + gp];
        for (int e = tid; e < CS*CO*9; e += 256) {
            int ci = e / (CO*9); int k = e - ci*(CO*9);
            ws[ci][k] = w3[(size_t)(coBase*9 + k)*C + cb + ci];
        }
        __syncthreads();
        #pragma unroll
        for (int ci = 0; ci < CS; ci++) {
            float v = in_s[ci][tid];
            #pragma unroll
            for (int k4 = 0; k4 < CO*9; k4 += 4) {
                float4 w4 = *(const float4*)&ws[ci][k4];
                facc[k4+0] += w4.x*v; facc[k4+1] += w4.y*v;
                facc[k4+2] += w4.z*v; facc[k4+3] += w4.w*v;
            }
        }
    }
    #pragma unroll
    for (int co = 0; co < CO; co++) {
        const float* x0c = g_x0 + (size_t)(b*C + coBase + co)*HW;
        float r = 0.f;
        #pragma unroll
        for (int t = 0; t < 9; t++) {
            int yy = y + t/3 - 1, xx = x + t%3 - 1;
            float u = (yy >= 0 && yy < H && xx >= 0 && xx < W) ? x0c[yy*W + xx] : 0.f;
            r += facc[co*9 + t] * u;
        }
        r = (r >= 0.f) ? r : 0.2f*r;
        g_out2[(size_t)(b*C + coBase + co)*HW + gp] = r;
    }
}

// ---------------- launch ----------------
extern "C" void kernel_launch(void* const* d_in, const int* in_sizes, int n_in,
                              void* d_out, int out_size) {
    const float* x       = (const float*)d_in[0];
    const float* offset  = (const float*)d_in[1];
    const float* conv0_w = (const float*)d_in[2];
    const float* conv0_b = (const float*)d_in[3];
    const float* offm_w  = (const float*)d_in[4];
    const float* offm_b  = (const float*)d_in[5];
    const float* dcn_w   = (const float*)d_in[6];
    const float* dcn_b   = (const float*)d_in[7];
    const float* a0_w    = (const float*)d_in[8];
    const float* a0_b    = (const float*)d_in[9];
    const float* a1_w    = (const float*)d_in[10];
    const float* a1_b    = (const float*)d_in[11];
    const float* a2_w    = (const float*)d_in[12];
    const float* a2_b    = (const float*)d_in[13];
    const float* a3_w    = (const float*)d_in[14];
    const float* a3_b    = (const float*)d_in[15];
    const float* fus_w   = (const float*)d_in[16];
    const float* fus_b   = (const float*)d_in[17];
    float* out = (float*)d_out;

    float *p_xc, *p_om, *p_x0, *p_xd, *p_out2;
    cudaGetSymbolAddress((void**)&p_xc, g_xc);
    cudaGetSymbolAddress((void**)&p_om, g_om);
    cudaGetSymbolAddress((void**)&p_x0, g_x0);
    cudaGetSymbolAddress((void**)&p_xd, g_xd);
    cudaGetSymbolAddress((void**)&p_out2, g_out2);

    // 1. conv0 1x1 (32->64)
    conv1x1_kernel<<<BB*HW/256, 256>>>(x, conv0_w, conv0_b);
    // 2. offset/mask conv 3x3 (32->216), sigmoid on mask channels
    conv3x3_kernel<CIN0,1><<<dim3(4,16,BB*14), 256>>>(offset, offm_w, offm_b, p_om, OMC, 14, nullptr);
    // 3. modulated deformable conv + lrelu
    deform_kernel<<<dim3(4,16,BB), 256>>>(dcn_w, dcn_b);
    // 4. a0 conv 3x3 (64->64)
    conv3x3_kernel<C,0><<<dim3(4,16,BB*4), 256>>>(p_xd, a0_w, a0_b, p_x0, C, 4, nullptr);
    // 5. channel means + eca
    mean_kernel<<<BB*C, 256>>>();
    eca_kernel<<<1, 256>>>(a2_w, a2_b);
    // 6. depthwise 3x3 + eca
    dw_kernel<<<BB*C*HW/256, 256>>>(a1_w, a1_b);
    // 7. fused a3 1x1 + unfold contraction + lrelu
    a3unfold_kernel<<<dim3(4,16,BB*(C/4)), 256>>>(a3_w, a3_b);
    // 8. fuse conv 3x3 + pre + x residuals (pre == x == xd, so +2*xd), write d_out
    conv3x3_kernel<C,2><<<dim3(4,16,BB*4), 256>>>(p_out2, fus_w, fus_b, out, C, 4, p_xd);
}

// round 8
// speedup vs baseline: 1.2763x; 1.2763x over previous
#include <cuda_runtime.h>
#include <math.h>

#define BB 4
#define C 64
#define CIN0 32
#define H 128
#define W 128
#define HW (H*W)
#define DG 8
#define CPG 8
#define OMC 216

// ---------------- scratch (device globals; no runtime allocation) ----------------
__device__ float g_xc[BB*C*HW];       // conv0 output
__device__ float g_om[BB*OMC*HW];     // offset/mask conv output
__device__ float g_xd[BB*C*HW];       // lrelu(deform conv) output
__device__ float g_x0[BB*C*HW];       // a0 conv output
__device__ float g_adcin[BB*C*HW];    // depthwise + eca
__device__ float g_out2[BB*C*HW];     // unfold*filt + lrelu output
__device__ float g_s[BB*C];           // channel means
__device__ float g_eca[BB*C];         // eca values

// ---------------- conv 1x1: x[BB,32,HW] -> g_xc[BB,64,HW] ----------------
__global__ void __launch_bounds__(256, 2) conv1x1_kernel(const float* __restrict__ in,
                                                         const float* __restrict__ w,
                                                         const float* __restrict__ bias) {
    __shared__ float ws[C*CIN0];
    int tid = threadIdx.x;
    for (int i = tid; i < C*CIN0; i += blockDim.x) ws[i] = w[i];
    __syncthreads();
    int p = blockIdx.x * blockDim.x + tid;
    int b = p / HW, pix = p % HW;
    float acc[C];
    #pragma unroll
    for (int co = 0; co < C; co++) acc[co] = bias[co];
    const float* xin = in + b*CIN0*HW + pix;
    #pragma unroll 4
    for (int ci = 0; ci < CIN0; ci += 4) {
        float v0 = xin[ci*HW], v1 = xin[(ci+1)*HW], v2 = xin[(ci+2)*HW], v3 = xin[(ci+3)*HW];
        #pragma unroll
        for (int co = 0; co < C; co++) {
            float4 w4 = *(const float4*)&ws[co*CIN0+ci];
            acc[co] += w4.x*v0 + w4.y*v1 + w4.z*v2 + w4.w*v3;
        }
    }
    float* o = g_xc + b*C*HW + pix;
    #pragma unroll
    for (int co = 0; co < C; co++) o[co*HW] = acc[co];
}

// ---------------- conv 3x3, pad=1 — 4 pixels/thread, full-width rows ----------------
// layout: warp w handles tile row y0+w (8 rows/block, full W=128 width),
// lane covers x = 4*lane .. 4*lane+3.  smem col = gx + 4 (left pad 4 => aligned float4).
// EPI: 0=none, 1=sigmoid on out-channels >=144 (offm), 2=+2*extra (fus)
template<int CI, int EPI>
__global__ void __launch_bounds__(256, 2) conv3x3_kernel(const float* __restrict__ in,
                               const float* __restrict__ wt,
                               const float* __restrict__ bias, float* __restrict__ out,
                               int Cout, int nchunk, const float* __restrict__ extra) {
    constexpr int CO = 16, CS = 4, RW = 136;   // smem row width (pad)
    __shared__ float in_s[CS][10][RW];
    __shared__ float ws[CS][CO][12];           // 9 weights padded to 12 for float4 reads
    int tid = threadIdx.x;
    int lane = tid & 31, warp = tid >> 5;
    int bz = blockIdx.z;
    int b = bz / nchunk, chunk = bz % nchunk;
    int coBase = chunk * CO;
    int y0 = blockIdx.y * 8;
    int y = y0 + warp;
    int xb = lane * 4;                          // first of 4 pixels

    float acc[CO][4];
    #pragma unroll
    for (int co = 0; co < CO; co++) {
        int gco = coBase + co;
        float bv = (gco < Cout) ? bias[gco] : 0.f;
        acc[co][0] = bv; acc[co][1] = bv; acc[co][2] = bv; acc[co][3] = bv;
    }

    for (int cb = 0; cb < CI; cb += CS) {
        __syncthreads();
        // stage CS channels x 10 rows x 130 cols (halo 1 each side), coalesced per row
        for (int r = warp; r < CS*10; r += 8) {
            int ci = r / 10, yy = r - ci*10;
            int gy = y0 + yy - 1;
            bool rowok = (gy >= 0 && gy < H);
            const float* src = in + ((size_t)(b*CI + cb + ci)*H + gy)*W;
            #pragma unroll
            for (int c = lane; c < RW; c += 32) {
                int gx = c - 4;
                float v = 0.f;
                if (rowok && gx >= 0 && gx < W) v = src[gx];
                in_s[ci][yy][c] = v;
            }
        }
        // stage weights: CS x CO x 9
        for (int e = tid; e < CS*CO*9; e += 256) {
            int ci = e / (CO*9); int r = e - ci*(CO*9); int co = r / 9; int t = r - co*9;
            int gco = coBase + co;
            ws[ci][co][t] = (gco < Cout) ? wt[((size_t)gco*CI + cb + ci)*9 + t] : 0.f;
        }
        __syncthreads();
        #pragma unroll
        for (int ci = 0; ci < CS; ci++) {
            // 3 rows x 6 cols window: aligned float4 + 2 scalars per row
            float v[3][6];
            #pragma unroll
            for (int dy = 0; dy < 3; dy++) {
                const float* row = &in_s[ci][warp+dy][0];
                float4 m = *(const float4*)&row[xb + 4];
                v[dy][0] = row[xb + 3];
                v[dy][1] = m.x; v[dy][2] = m.y; v[dy][3] = m.z; v[dy][4] = m.w;
                v[dy][5] = row[xb + 8];
            }
            #pragma unroll
            for (int co = 0; co < CO; co++) {
                const float* wp = &ws[ci][co][0];
                float4 wa = *(const float4*)wp;
                float4 wb = *(const float4*)(wp+4);
                float w8 = wp[8];
                float wk[9] = {wa.x, wa.y, wa.z, wa.w, wb.x, wb.y, wb.z, wb.w, w8};
                #pragma unroll
                for (int dy = 0; dy < 3; dy++)
                    #pragma unroll
                    for (int dx = 0; dx < 3; dx++) {
                        float wv = wk[dy*3+dx];
                        acc[co][0] += wv * v[dy][dx];
                        acc[co][1] += wv * v[dy][dx+1];
                        acc[co][2] += wv * v[dy][dx+2];
                        acc[co][3] += wv * v[dy][dx+3];
                    }
            }
        }
    }
    size_t gp = (size_t)y*W + xb;
    #pragma unroll
    for (int co = 0; co < CO; co++) {
        int gco = coBase + co;
        if (gco < Cout) {
            float4 r = make_float4(acc[co][0], acc[co][1], acc[co][2], acc[co][3]);
            if (EPI == 1) {
                if (gco >= 144) {
                    r.x = 1.f/(1.f+expf(-r.x)); r.y = 1.f/(1.f+expf(-r.y));
                    r.z = 1.f/(1.f+expf(-r.z)); r.w = 1.f/(1.f+expf(-r.w));
                }
            }
            if (EPI == 2) {
                float4 e4 = *(const float4*)&extra[(size_t)(b*C + gco)*HW + gp];
                r.x += 2.f*e4.x; r.y += 2.f*e4.y; r.z += 2.f*e4.z; r.w += 2.f*e4.w;
            }
            *(float4*)&out[((size_t)(b*Cout) + gco)*HW + gp] = r;
        }
    }
}

// ---------------- modulated deformable conv + lrelu ----------------
__global__ void __launch_bounds__(256, 2) deform_kernel(const float* __restrict__ wt,
                                                        const float* __restrict__ bias) {
    __shared__ float ws[9*CPG*C];   // [t][cic][co], staged per group (18KB)
    int tid = threadIdx.x;
    int tx = tid & 31, ty = tid >> 5;
    int b = blockIdx.z;
    int x = blockIdx.x*32 + tx, y = blockIdx.y*8 + ty;
    int p = y*W + x;

    float acc[C];
    #pragma unroll
    for (int co = 0; co < C; co++) acc[co] = bias[co];

    for (int g = 0; g < DG; g++) {
        __syncthreads();
        for (int e = tid; e < 9*CPG*C; e += 256) {
            int t = e / (CPG*C); int r = e - t*(CPG*C); int cic = r >> 6; int co = r & 63;
            ws[e] = wt[((size_t)co*C + g*CPG + cic)*9 + t];
        }
        __syncthreads();
        const float* omb = g_om + (size_t)b*OMC*HW;
        const float* xb = g_xc + (size_t)(b*C + g*CPG)*HW;
        for (int t = 0; t < 9; t++) {
            float dy = omb[(size_t)(g*9 + t)*HW + p];
            float dx = omb[(size_t)(72 + g*9 + t)*HW + p];
            float mk = omb[(size_t)(144 + g*9 + t)*HW + p];
            float py = dy + (float)(t/3) + (float)y - 1.0f;
            float px = dx + (float)(t%3) + (float)x - 1.0f;
            float fy = floorf(py), fx = floorf(px);
            int iy0 = (int)fy, ix0 = (int)fx;
            float wy = py - fy, wx = px - fx;
            bool vy0 = (iy0 >= 0 && iy0 < H), vy1 = (iy0+1 >= 0 && iy0+1 < H);
            bool vx0 = (ix0 >= 0 && ix0 < W), vx1 = (ix0+1 >= 0 && ix0+1 < W);
            int cy0 = min(max(iy0, 0), H-1), cy1 = min(max(iy0+1, 0), H-1);
            int cx0 = min(max(ix0, 0), W-1), cx1 = min(max(ix0+1, 0), W-1);
            float a00 = (vy0 && vx0) ? (1.f-wy)*(1.f-wx)*mk : 0.f;
            float a01 = (vy0 && vx1) ? (1.f-wy)*wx*mk       : 0.f;
            float a10 = (vy1 && vx0) ? wy*(1.f-wx)*mk       : 0.f;
            float a11 = (vy1 && vx1) ? wy*wx*mk             : 0.f;
            int i00 = cy0*W + cx0, i01 = cy0*W + cx1, i10 = cy1*W + cx0, i11 = cy1*W + cx1;
            #pragma unroll
            for (int cic = 0; cic < CPG; cic++) {
                const float* xc = xb + (size_t)cic*HW;
                float s = a00*xc[i00] + a01*xc[i01] + a10*xc[i10] + a11*xc[i11];
                const float* wp = &ws[(t*CPG + cic)*C];
                #pragma unroll
                for (int co4 = 0; co4 < C; co4 += 4) {
                    float4 w4 = *(const float4*)(wp + co4);
                    acc[co4+0] += w4.x*s; acc[co4+1] += w4.y*s;
                    acc[co4+2] += w4.z*s; acc[co4+3] += w4.w*s;
                }
            }
        }
    }
    float* ob = g_xd + (size_t)b*C*HW + p;
    #pragma unroll
    for (int co = 0; co < C; co++) {
        float r = acc[co];
        r = (r >= 0.f) ? r : 0.2f*r;
        ob[(size_t)co*HW] = r;
    }
}

// ---------------- mean over H,W per (b,c) ----------------
__global__ void __launch_bounds__(256) mean_kernel() {
    int bc = blockIdx.x;
    const float* pp = g_x0 + (size_t)bc*HW;
    float sum = 0.f;
    for (int i = threadIdx.x; i < HW; i += 256) sum += pp[i];
    __shared__ float red[256];
    red[threadIdx.x] = sum; __syncthreads();
    for (int st = 128; st > 0; st >>= 1) {
        if (threadIdx.x < st) red[threadIdx.x] += red[threadIdx.x + st];
        __syncthreads();
    }
    if (threadIdx.x == 0) g_s[bc] = red[0] * (1.0f/HW);
}

// ---------------- eca: conv1d(k=3,pad=1) over channels ----------------
__global__ void eca_kernel(const float* __restrict__ a2w, const float* __restrict__ a2b) {
    int i = threadIdx.x;
    if (i < BB*C) {
        int b = i / C, c = i % C;
        float l = (c > 0)     ? g_s[b*C + c - 1] : 0.f;
        float m = g_s[b*C + c];
        float r = (c < C - 1) ? g_s[b*C + c + 1] : 0.f;
        g_eca[i] = a2w[0]*l + a2w[1]*m + a2w[2]*r + a2b[0];
    }
}

// ---------------- depthwise 3x3 + eca broadcast ----------------
__global__ void __launch_bounds__(256) dw_kernel(const float* __restrict__ w,
                                                 const float* __restrict__ bias) {
    int idx = blockIdx.x*256 + threadIdx.x;
    int p = idx % HW; int bc = idx / HW; int c = bc % C;
    int y = p / W, x = p % W;
    const float* in = g_x0 + (size_t)bc*HW;
    float acc = bias[c] + g_eca[bc];
    #pragma unroll
    for (int t = 0; t < 9; t++) {
        int yy = y + t/3 - 1, xx = x + t%3 - 1;
        if (yy >= 0 && yy < H && xx >= 0 && xx < W) acc += w[c*9 + t] * in[yy*W + xx];
    }
    g_adcin[idx] = acc;
}

// ---------------- fused a3 (1x1 -> C*9) + unfold(x0)*filt + lrelu ----------------
__global__ void __launch_bounds__(256, 2) a3unfold_kernel(const float* __restrict__ w3,
                                                          const float* __restrict__ b3) {
    constexpr int CO = 4, CS = 8;
    __shared__ float in_s[CS][256];
    __shared__ float ws[CS][CO*9];
    int tid = threadIdx.x;
    int tx = tid & 31, ty = tid >> 5;
    int bz = blockIdx.z;
    int b = bz / (C/CO), coBase = (bz % (C/CO)) * CO;
    int x = blockIdx.x*32 + tx, y = blockIdx.y*8 + ty;
    int gp = y*W + x;

    float facc[CO*9];
    #pragma unroll
    for (int k = 0; k < CO*9; k++) facc[k] = b3[coBase*9 + k];

    for (int cb = 0; cb < C; cb += CS) {
        __syncthreads();
        #pragma unroll
        for (int ci = 0; ci < CS; ci++)
            in_s[ci][tid] = g_adcin[(size_t)(b*C + cb + ci)*HW + gp];
        for (int e = tid; e < CS*CO*9; e += 256) {
            int ci = e / (CO*9); int k = e - ci*(CO*9);
            ws[ci][k] = w3[(size_t)(coBase*9 + k)*C + cb + ci];
        }
        __syncthreads();
        #pragma unroll
        for (int ci = 0; ci < CS; ci++) {
            float v = in_s[ci][tid];
            #pragma unroll
            for (int k4 = 0; k4 < CO*9; k4 += 4) {
                float4 w4 = *(const float4*)&ws[ci][k4];
                facc[k4+0] += w4.x*v; facc[k4+1] += w4.y*v;
                facc[k4+2] += w4.z*v; facc[k4+3] += w4.w*v;
            }
        }
    }
    #pragma unroll
    for (int co = 0; co < CO; co++) {
        const float* x0c = g_x0 + (size_t)(b*C + coBase + co)*HW;
        float r = 0.f;
        #pragma unroll
        for (int t = 0; t < 9; t++) {
            int yy = y + t/3 - 1, xx = x + t%3 - 1;
            float u = (yy >= 0 && yy < H && xx >= 0 && xx < W) ? x0c[yy*W + xx] : 0.f;
            r += facc[co*9 + t] * u;
        }
        r = (r >= 0.f) ? r : 0.2f*r;
        g_out2[(size_t)(b*C + coBase + co)*HW + gp] = r;
    }
}

// ---------------- launch ----------------
extern "C" void kernel_launch(void* const* d_in, const int* in_sizes, int n_in,
                              void* d_out, int out_size) {
    const float* x       = (const float*)d_in[0];
    const float* offset  = (const float*)d_in[1];
    const float* conv0_w = (const float*)d_in[2];
    const float* conv0_b = (const float*)d_in[3];
    const float* offm_w  = (const float*)d_in[4];
    const float* offm_b  = (const float*)d_in[5];
    const float* dcn_w   = (const float*)d_in[6];
    const float* dcn_b   = (const float*)d_in[7];
    const float* a0_w    = (const float*)d_in[8];
    const float* a0_b    = (const float*)d_in[9];
    const float* a1_w    = (const float*)d_in[10];
    const float* a1_b    = (const float*)d_in[11];
    const float* a2_w    = (const float*)d_in[12];
    const float* a2_b    = (const float*)d_in[13];
    const float* a3_w    = (const float*)d_in[14];
    const float* a3_b    = (const float*)d_in[15];
    const float* fus_w   = (const float*)d_in[16];
    const float* fus_b   = (const float*)d_in[17];
    float* out = (float*)d_out;

    float *p_xc, *p_om, *p_x0, *p_xd, *p_out2;
    cudaGetSymbolAddress((void**)&p_xc, g_xc);
    cudaGetSymbolAddress((void**)&p_om, g_om);
    cudaGetSymbolAddress((void**)&p_x0, g_x0);
    cudaGetSymbolAddress((void**)&p_xd, g_xd);
    cudaGetSymbolAddress((void**)&p_out2, g_out2);

    // 1. conv0 1x1 (32->64)
    conv1x1_kernel<<<BB*HW/256, 256>>>(x, conv0_w, conv0_b);
    // 2. offset/mask conv 3x3 (32->216), sigmoid on mask channels
    conv3x3_kernel<CIN0,1><<<dim3(1,16,BB*14), 256>>>(offset, offm_w, offm_b, p_om, OMC, 14, nullptr);
    // 3. modulated deformable conv + lrelu
    deform_kernel<<<dim3(4,16,BB), 256>>>(dcn_w, dcn_b);
    // 4. a0 conv 3x3 (64->64)
    conv3x3_kernel<C,0><<<dim3(1,16,BB*4), 256>>>(p_xd, a0_w, a0_b, p_x0, C, 4, nullptr);
    // 5. channel means + eca
    mean_kernel<<<BB*C, 256>>>();
    eca_kernel<<<1, 256>>>(a2_w, a2_b);
    // 6. depthwise 3x3 + eca
    dw_kernel<<<BB*C*HW/256, 256>>>(a1_w, a1_b);
    // 7. fused a3 1x1 + unfold contraction + lrelu
    a3unfold_kernel<<<dim3(4,16,BB*(C/4)), 256>>>(a3_w, a3_b);
    // 8. fuse conv 3x3 + pre + x residuals (pre == x == xd, so +2*xd), write d_out
    conv3x3_kernel<C,2><<<dim3(1,16,BB*4), 256>>>(p_out2, fus_w, fus_b, out, C, 4, p_xd);
}